// round 3
// baseline (speedup 1.0000x reference)
#include <cuda_runtime.h>
#include <math.h>

typedef unsigned long long u64;

#define CC 32
#define KK 19
#define KP 20

// ---- folded-constant buffer layout (floats) ----
#define OFF_W1   0      // 1024  [d*32+c]  select_w1 * bn_scale[c]
#define OFF_WQ   1024   // 1024  [d*32+c]  wq
#define OFF_BKT  2048   // 640   [c*20+k]  BK[k,c] = base[k]@wk  (pad k=19 -> 0)
#define OFF_BV   2688   // 608   [k*32+c]  BV[k,c] = base[k]@wv
#define OFF_WT1  3296   // 640   [c*20+k]  wt[:32]@w_out
#define OFF_WOT  3936   // 640   [c*20+k]  wo@(wt[32:]@w_out)
#define OFF_WSK  4576   // 96    [j*32+c]  ws@wk
#define OFF_WSV  4672   // 96    [j*32+c]  ws@wv
#define OFF_BQ   4768   // 32
#define OFF_BK   4800   // 32
#define OFF_BVB  4832   // 32    bv
#define OFF_W2   4864   // 32    select_w2
#define OFF_B1F  4896   // 32    folded BN bias
#define OFF_BOUT 4928   // 20    bt@w_out + b_out (pad 0)
#define OFF_BOT  4948   // 20    bo@(wt[32:]@w_out) (pad 0)
#define OFF_SCAL 4968   // 8     [b2, 0...]
#define BUF_SZ   4976

__device__ __align__(16) float g_buf[BUF_SZ];

__device__ __forceinline__ u64 ffma2(u64 a, u64 b, u64 c) {
    u64 d; asm("fma.rn.f32x2 %0, %1, %2, %3;" : "=l"(d) : "l"(a), "l"(b), "l"(c)); return d;
}
__device__ __forceinline__ u64 pack2(float x, float y) {
    u64 r; asm("mov.b64 %0, {%1, %2};" : "=l"(r) : "f"(x), "f"(y)); return r;
}
__device__ __forceinline__ void unpack2(u64 v, float& x, float& y) {
    asm("mov.b64 {%0, %1}, %2;" : "=f"(x), "=f"(y) : "l"(v));
}

// ============================================================================
// Setup kernel: fold all weights. 1 block, 1024 threads, ~100K MACs total.
// ============================================================================
__global__ void setup_kernel(
    const float* __restrict__ z, const float* __restrict__ select_w1,
    const float* __restrict__ bn_gamma, const float* __restrict__ bn_beta,
    const float* __restrict__ bn_mean, const float* __restrict__ bn_var,
    const float* __restrict__ select_w2, const float* __restrict__ select_b2,
    const float* __restrict__ wq, const float* __restrict__ bq,
    const float* __restrict__ wk, const float* __restrict__ bk,
    const float* __restrict__ wv, const float* __restrict__ bv,
    const float* __restrict__ wo, const float* __restrict__ bo,
    const float* __restrict__ wt, const float* __restrict__ bt,
    const float* __restrict__ w_out, const float* __restrict__ b_out,
    const float* __restrict__ w_gen, const float* __restrict__ b_gen)
{
    __shared__ float s_zw[32];
    __shared__ float s_base[19 * 32];
    __shared__ float s_Wt2[32 * KP];
    const int t = threadIdx.x;

    // ---- phase 1: things independent of s_base ----
    if (t < 32) {
        float acc = b_gen[t];
        #pragma unroll
        for (int i = 0; i < 16; ++i) acc += z[i] * w_gen[i * 32 + t];
        s_zw[t] = acc;
        float sc = bn_gamma[t] * rsqrtf(bn_var[t] + 1e-4f);
        g_buf[OFF_B1F + t] = bn_beta[t] - bn_mean[t] * sc;
        g_buf[OFF_BQ + t]  = bq[t];
        g_buf[OFF_BK + t]  = bk[t];
        g_buf[OFF_BVB + t] = bv[t];
        g_buf[OFF_W2 + t]  = select_w2[t];
    }
    if (t < 8) g_buf[OFF_SCAL + t] = (t == 0) ? select_b2[0] : 0.0f;
    {   // W1 folded + WQ copy (1024 entries each)
        int d = t >> 5, c = t & 31;
        float sc = bn_gamma[c] * rsqrtf(bn_var[c] + 1e-4f);
        g_buf[OFF_W1 + t] = select_w1[d * 32 + c] * sc;
        g_buf[OFF_WQ + t] = wq[t];
    }
    if (t < 96) {
        int j = t / 32, c = t % 32;
        float aK = 0.f, aV = 0.f;
        #pragma unroll
        for (int d = 0; d < 32; ++d) {
            float w = w_gen[(35 + j) * 32 + d];
            aK += w * wk[d * 32 + c];
            aV += w * wv[d * 32 + c];
        }
        g_buf[OFF_WSK + t] = aK;
        g_buf[OFF_WSV + t] = aV;
    }
    if (t < 640) {   // Wt1 (feat path) and Wt2 (new_feat path, temp)
        int c = t / KP, k = t % KP;
        float a1 = 0.f, a2 = 0.f;
        if (k < KK) {
            #pragma unroll
            for (int e = 0; e < 32; ++e) {
                a1 += wt[c * 32 + e]        * w_out[e * KK + k];
                a2 += wt[(32 + c) * 32 + e] * w_out[e * KK + k];
            }
        }
        g_buf[OFF_WT1 + t] = a1;
        s_Wt2[t] = a2;
    }
    if (t < 20) {
        float a = 0.f;
        if (t < KK) {
            a = b_out[t];
            #pragma unroll
            for (int e = 0; e < 32; ++e) a += bt[e] * w_out[e * KK + t];
        }
        g_buf[OFF_BOUT + t] = a;
    }
    __syncthreads();

    // ---- phase 2: base, WoT, boT ----
    if (t < 608) {
        int k = t / 32, c = t % 32;
        s_base[t] = s_zw[c] + w_gen[(16 + k) * 32 + c];
    }
    if (t < 640) {
        int c = t / KP, k = t % KP;
        float a = 0.f;
        if (k < KK) {
            #pragma unroll
            for (int d = 0; d < 32; ++d) a += wo[c * 32 + d] * s_Wt2[d * KP + k];
        }
        g_buf[OFF_WOT + t] = a;
    }
    if (t < 20) {
        float a = 0.f;
        if (t < KK) {
            #pragma unroll
            for (int d = 0; d < 32; ++d) a += bo[d] * s_Wt2[d * KP + t];
        }
        g_buf[OFF_BOT + t] = a;
    }
    __syncthreads();

    // ---- phase 3: BK (transposed) and BV ----
    if (t < 640) {
        int c = t / KP, k = t % KP;
        float a = 0.f;
        if (k < KK) {
            #pragma unroll
            for (int d = 0; d < 32; ++d) a += s_base[k * 32 + d] * wk[d * 32 + c];
        }
        g_buf[OFF_BKT + t] = a;
    }
    if (t < 608) {
        int k = t / 32, c = t % 32;
        float a = 0.f;
        #pragma unroll
        for (int d = 0; d < 32; ++d) a += s_base[k * 32 + d] * wv[d * 32 + c];
        g_buf[OFF_BV + t] = a;
    }
}

// ============================================================================
// Main kernel: one thread per point.
// ============================================================================
__global__ void __launch_bounds__(256, 2) refine_kernel(
    const float* __restrict__ feat,
    const float* __restrict__ sflow,
    const float* __restrict__ cpred,
    float* __restrict__ out,
    int N)
{
    __shared__ __align__(16) float sw[BUF_SZ];
    #pragma unroll 2
    for (int i = threadIdx.x; i < BUF_SZ / 4; i += 256)
        reinterpret_cast<float4*>(sw)[i] = reinterpret_cast<const float4*>(g_buf)[i];
    __syncthreads();

    const int n = blockIdx.x * 256 + threadIdx.x;
    if (n >= N) return;

    // ---- coarse_pred softmax ----
    float cp[KK];
    {
        const float* cpp = cpred + (size_t)n * KK;
        float m = -1e30f;
        #pragma unroll
        for (int k = 0; k < KK; ++k) { cp[k] = cpp[k]; m = fmaxf(m, cp[k]); }
        float s = 0.f;
        #pragma unroll
        for (int k = 0; k < KK; ++k) { cp[k] = __expf(cp[k] - m); s += cp[k]; }
        float inv = 1.f / s;
        #pragma unroll
        for (int k = 0; k < KK; ++k) cp[k] *= inv;
    }

    // ---- feat row ----
    float f[32];
    {
        const float4* fp = reinterpret_cast<const float4*>(feat + (size_t)n * 32);
        #pragma unroll
        for (int i = 0; i < 8; ++i) {
            float4 v = fp[i];
            f[4 * i] = v.x; f[4 * i + 1] = v.y; f[4 * i + 2] = v.z; f[4 * i + 3] = v.w;
        }
    }
    const float* sfp = sflow + (size_t)n * 3;
    const float s0 = sfp[0], s1 = sfp[1], s2v = sfp[2];

    // ---- h = relu(BN(feat@w1)) ; score ----
    bool valid;
    {
        u64 hA[16];
        #pragma unroll
        for (int t = 0; t < 16; ++t) hA[t] = 0ull;
        #pragma unroll
        for (int d = 0; d < 32; ++d) {
            u64 fd2 = pack2(f[d], f[d]);
            const ulonglong2* w = reinterpret_cast<const ulonglong2*>(sw + OFF_W1 + d * 32);
            #pragma unroll
            for (int t = 0; t < 8; ++t) {
                ulonglong2 ww = w[t];
                hA[2 * t]     = ffma2(ww.x, fd2, hA[2 * t]);
                hA[2 * t + 1] = ffma2(ww.y, fd2, hA[2 * t + 1]);
            }
        }
        float slin = sw[OFF_SCAL];
        #pragma unroll
        for (int t = 0; t < 16; ++t) {
            float a, b; unpack2(hA[t], a, b);
            a = fmaxf(a + sw[OFF_B1F + 2 * t], 0.f);
            b = fmaxf(b + sw[OFF_B1F + 2 * t + 1], 0.f);
            slin += a * sw[OFF_W2 + 2 * t] + b * sw[OFF_W2 + 2 * t + 1];
        }
        float score = 1.f / (1.f + expf(-slin));
        bool tmask = (s0 != 0.f) || (s1 != 0.f) || (s2v != 0.f);
        valid = (score < 0.8f) && tmask;
    }

    // ---- q = feat@wq + bq ----
    float q[32];
    {
        u64 qA[16];
        #pragma unroll
        for (int t = 0; t < 16; ++t) qA[t] = 0ull;
        #pragma unroll
        for (int d = 0; d < 32; ++d) {
            u64 fd2 = pack2(f[d], f[d]);
            const ulonglong2* w = reinterpret_cast<const ulonglong2*>(sw + OFF_WQ + d * 32);
            #pragma unroll
            for (int t = 0; t < 8; ++t) {
                ulonglong2 ww = w[t];
                qA[2 * t]     = ffma2(ww.x, fd2, qA[2 * t]);
                qA[2 * t + 1] = ffma2(ww.y, fd2, qA[2 * t + 1]);
            }
        }
        #pragma unroll
        for (int t = 0; t < 16; ++t) {
            unpack2(qA[t], q[2 * t], q[2 * t + 1]);
            q[2 * t]     += sw[OFF_BQ + 2 * t];
            q[2 * t + 1] += sw[OFF_BQ + 2 * t + 1];
        }
    }

    // ---- q·sK and q·bk ----
    float qsK = 0.f, qbk = 0.f;
    #pragma unroll
    for (int c = 0; c < 32; ++c) {
        float kc = s0 * sw[OFF_WSK + c] + s1 * sw[OFF_WSK + 32 + c] + s2v * sw[OFF_WSK + 64 + c];
        qsK += q[c] * kc;
        qbk += q[c] * sw[OFF_BK + c];
    }

    // ---- attention logits: qBK[k] ----
    float a2[KK]; float s2;
    {
        u64 L[10];
        #pragma unroll
        for (int t = 0; t < 10; ++t) L[t] = 0ull;
        #pragma unroll
        for (int c = 0; c < 32; ++c) {
            u64 qc2 = pack2(q[c], q[c]);
            const ulonglong2* r = reinterpret_cast<const ulonglong2*>(sw + OFF_BKT + c * KP);
            #pragma unroll
            for (int t = 0; t < 5; ++t) {
                ulonglong2 ww = r[t];
                L[2 * t]     = ffma2(ww.x, qc2, L[2 * t]);
                L[2 * t + 1] = ffma2(ww.y, qc2, L[2 * t + 1]);
            }
        }
        float lg[20];
        #pragma unroll
        for (int t = 0; t < 10; ++t) unpack2(L[t], lg[2 * t], lg[2 * t + 1]);
        const float rsC = 0.17677669529663687f;   // 1/sqrt(32)
        float m = -1e30f;
        #pragma unroll
        for (int k = 0; k < KK; ++k) {
            lg[k] = (cp[k] * (lg[k] + qsK) + qbk) * rsC;
            m = fmaxf(m, lg[k]);
        }
        float S = 0.f;
        #pragma unroll
        for (int k = 0; k < KK; ++k) { lg[k] = __expf(lg[k] - m); S += lg[k]; }
        float invS = 1.f / S;
        s2 = 0.f;
        #pragma unroll
        for (int k = 0; k < KK; ++k) { a2[k] = lg[k] * invS * cp[k]; s2 += a2[k]; }
    }

    // ---- aug_pre = sum_k a2[k]*BV[k,:] + s2*sV + bv ----
    float aug[32];
    {
        u64 A[16];
        #pragma unroll
        for (int t = 0; t < 16; ++t) A[t] = 0ull;
        #pragma unroll
        for (int k = 0; k < KK; ++k) {
            u64 ak2 = pack2(a2[k], a2[k]);
            const ulonglong2* r = reinterpret_cast<const ulonglong2*>(sw + OFF_BV + k * 32);
            #pragma unroll
            for (int t = 0; t < 8; ++t) {
                ulonglong2 ww = r[t];
                A[2 * t]     = ffma2(ww.x, ak2, A[2 * t]);
                A[2 * t + 1] = ffma2(ww.y, ak2, A[2 * t + 1]);
            }
        }
        #pragma unroll
        for (int t = 0; t < 16; ++t) unpack2(A[t], aug[2 * t], aug[2 * t + 1]);
        float vf = valid ? 1.f : 0.f;
        #pragma unroll
        for (int c = 0; c < 32; ++c) {
            float sVc = s0 * sw[OFF_WSV + c] + s1 * sw[OFF_WSV + 32 + c] + s2v * sw[OFF_WSV + 64 + c];
            aug[c] = vf * (aug[c] + s2 * sVc + sw[OFF_BVB + c]);
        }
    }

    // ---- out = feat@Wt1 + bout + (valid ? aug@WoT + boT : 0) ----
    {
        u64 O[10];
        const u64* bp = reinterpret_cast<const u64*>(sw + OFF_BOUT);
        #pragma unroll
        for (int t = 0; t < 10; ++t) O[t] = bp[t];
        float vf = valid ? 1.f : 0.f;
        u64 vf2 = pack2(vf, vf);
        const ulonglong2* bb = reinterpret_cast<const ulonglong2*>(sw + OFF_BOT);
        #pragma unroll
        for (int t = 0; t < 5; ++t) {
            ulonglong2 ww = bb[t];
            O[2 * t]     = ffma2(ww.x, vf2, O[2 * t]);
            O[2 * t + 1] = ffma2(ww.y, vf2, O[2 * t + 1]);
        }
        #pragma unroll
        for (int c = 0; c < 32; ++c) {
            u64 fc2 = pack2(f[c], f[c]);
            const ulonglong2* r1 = reinterpret_cast<const ulonglong2*>(sw + OFF_WT1 + c * KP);
            #pragma unroll
            for (int t = 0; t < 5; ++t) {
                ulonglong2 ww = r1[t];
                O[2 * t]     = ffma2(ww.x, fc2, O[2 * t]);
                O[2 * t + 1] = ffma2(ww.y, fc2, O[2 * t + 1]);
            }
            u64 ac2 = pack2(aug[c], aug[c]);
            const ulonglong2* r2 = reinterpret_cast<const ulonglong2*>(sw + OFF_WOT + c * KP);
            #pragma unroll
            for (int t = 0; t < 5; ++t) {
                ulonglong2 ww = r2[t];
                O[2 * t]     = ffma2(ww.x, ac2, O[2 * t]);
                O[2 * t + 1] = ffma2(ww.y, ac2, O[2 * t + 1]);
            }
        }
        float o[20];
        #pragma unroll
        for (int t = 0; t < 10; ++t) unpack2(O[t], o[2 * t], o[2 * t + 1]);
        float* op = out + (size_t)n * KK;
        #pragma unroll
        for (int k = 0; k < KK; ++k) op[k] = o[k];
    }
}

// ============================================================================
extern "C" void kernel_launch(void* const* d_in, const int* in_sizes, int n_in,
                              void* d_out, int out_size)
{
    const float* feat      = (const float*)d_in[0];
    const float* sflow     = (const float*)d_in[1];
    const float* cpred     = (const float*)d_in[2];
    const float* z         = (const float*)d_in[3];
    const float* select_w1 = (const float*)d_in[4];
    const float* bn_gamma  = (const float*)d_in[5];
    const float* bn_beta   = (const float*)d_in[6];
    const float* bn_mean   = (const float*)d_in[7];
    const float* bn_var    = (const float*)d_in[8];
    const float* select_w2 = (const float*)d_in[9];
    const float* select_b2 = (const float*)d_in[10];
    const float* wq        = (const float*)d_in[11];
    const float* bq        = (const float*)d_in[12];
    const float* wk        = (const float*)d_in[13];
    const float* bk        = (const float*)d_in[14];
    const float* wv        = (const float*)d_in[15];
    const float* bv        = (const float*)d_in[16];
    const float* wo        = (const float*)d_in[17];
    const float* bo        = (const float*)d_in[18];
    const float* wt        = (const float*)d_in[19];
    const float* bt        = (const float*)d_in[20];
    const float* w_out     = (const float*)d_in[21];
    const float* b_out     = (const float*)d_in[22];
    const float* w_gen     = (const float*)d_in[23];
    const float* b_gen     = (const float*)d_in[24];
    float* out = (float*)d_out;

    const int N = in_sizes[0] / 32;

    setup_kernel<<<1, 1024>>>(z, select_w1, bn_gamma, bn_beta, bn_mean, bn_var,
                              select_w2, select_b2, wq, bq, wk, bk, wv, bv,
                              wo, bo, wt, bt, w_out, b_out, w_gen, b_gen);

    refine_kernel<<<(N + 255) / 256, 256>>>(feat, sflow, cpred, out, N);
}

// round 4
// speedup vs baseline: 1.2863x; 1.2863x over previous
#include <cuda_runtime.h>
#include <math.h>

typedef unsigned long long u64;

#define KK 19
#define KP 20

// ---- folded-constant buffer layout (floats) ----
// SW1 : 1024  [d*32+c]   select_w1 * bn_scale[c]
// SFB : 1408  [d*44+..]  cols 0..19: M1=rsC*wq@BK^T (pad), 20..23: M2=rsC*wq@[sK0,sK1,sK2,bk],
//                        cols 24..43: WT1 = wt[:32]@w_out (pad)
// SG  : 400   [k'*20+k]  G = BV@Wo2
// SP  : 80    [j*20+k]   rows 0..2: sV_j@Wo2 ; row 3: bv@Wo2 + bo@WoT2
// SC1 : 20    cM1 = rsC*bq@BK^T
// SC2 : 4     cM2
// SBOUT:20    b_out + bt@w_out
// SB1F: 32    folded BN bias
// SW2 : 32    select_w2
// SB2 : 4     select_b2
#define SW1   0
#define SFB   1024
#define SG    2432
#define SP    2832
#define SC1   2912
#define SC2   2932
#define SBOUT 2936
#define SB1F  2956
#define SW2   2988
#define SB2   3020
#define BUF_SZ 3024

__device__ __align__(16) float g_buf[BUF_SZ];

__device__ __forceinline__ u64 ffma2(u64 a, u64 b, u64 c) {
    u64 d; asm("fma.rn.f32x2 %0, %1, %2, %3;" : "=l"(d) : "l"(a), "l"(b), "l"(c)); return d;
}
__device__ __forceinline__ u64 pack2(float x, float y) {
    u64 r; asm("mov.b64 %0, {%1, %2};" : "=l"(r) : "f"(x), "f"(y)); return r;
}
__device__ __forceinline__ void unpack2(u64 v, float& x, float& y) {
    asm("mov.b64 {%0, %1}, %2;" : "=f"(x), "=f"(y) : "l"(v));
}

// ============================================================================
// Setup kernel: fold all weights. 1 block, 1024 threads, ~200K MACs.
// ============================================================================
__global__ void setup_kernel(
    const float* __restrict__ z, const float* __restrict__ select_w1,
    const float* __restrict__ bn_gamma, const float* __restrict__ bn_beta,
    const float* __restrict__ bn_mean, const float* __restrict__ bn_var,
    const float* __restrict__ select_w2, const float* __restrict__ select_b2,
    const float* __restrict__ wq, const float* __restrict__ bq,
    const float* __restrict__ wk, const float* __restrict__ bk,
    const float* __restrict__ wv, const float* __restrict__ bv,
    const float* __restrict__ wo, const float* __restrict__ bo,
    const float* __restrict__ wt, const float* __restrict__ bt,
    const float* __restrict__ w_out, const float* __restrict__ b_out,
    const float* __restrict__ w_gen, const float* __restrict__ b_gen)
{
    __shared__ float s_zw[32];
    __shared__ float s_sK[96], s_sV[96];
    __shared__ float s_WoT2[640], s_Wo2[640];
    __shared__ float s_base[608];
    __shared__ float s_BK[608], s_BV[608];
    const int t = threadIdx.x;
    const float rsC = 0.17677669529663687f;  // 1/sqrt(32)

    // -------- Stage 0 --------
    {   // W1 folded with BN scale (all 1024 threads)
        int c = t & 31;
        float sc = bn_gamma[c] * rsqrtf(bn_var[c] + 1e-4f);
        g_buf[SW1 + t] = select_w1[t] * sc;
    }
    if (t < 32) {
        float acc = b_gen[t];
        #pragma unroll
        for (int i = 0; i < 16; ++i) acc += z[i] * w_gen[i * 32 + t];
        s_zw[t] = acc;
        float sc = bn_gamma[t] * rsqrtf(bn_var[t] + 1e-4f);
        g_buf[SB1F + t] = bn_beta[t] - bn_mean[t] * sc;
        g_buf[SW2 + t]  = select_w2[t];
    }
    if (t == 32) g_buf[SB2] = select_b2[0];
    if (t < 96) {
        int j = t / 32, c = t % 32;
        float aK = 0.f, aV = 0.f;
        #pragma unroll
        for (int d = 0; d < 32; ++d) {
            float w = w_gen[(35 + j) * 32 + d];
            aK += w * wk[d * 32 + c];
            aV += w * wv[d * 32 + c];
        }
        s_sK[t] = aK; s_sV[t] = aV;
    }
    if (t < 640) {   // WT1 -> g_buf cols 24..43 ; WoT2 -> smem
        int d = t / KP, k = t % KP;
        float a1 = 0.f, a2w = 0.f;
        if (k < KK) {
            #pragma unroll
            for (int e = 0; e < 32; ++e) {
                a1  += wt[d * 32 + e]        * w_out[e * KK + k];
                a2w += wt[(32 + d) * 32 + e] * w_out[e * KK + k];
            }
        }
        g_buf[SFB + d * 44 + 24 + k] = a1;
        s_WoT2[t] = a2w;
    }
    if (t >= 640 && t < 660) {
        int k = t - 640; float a = 0.f;
        if (k < KK) {
            a = b_out[k];
            #pragma unroll
            for (int e = 0; e < 32; ++e) a += bt[e] * w_out[e * KK + k];
        }
        g_buf[SBOUT + k] = a;
    }
    __syncthreads();

    // -------- Stage 1: base, Wo2 --------
    if (t < 608)
        s_base[t] = s_zw[t & 31] + w_gen[(16 + (t >> 5)) * 32 + (t & 31)];
    if (t < 640) {
        int c = t / KP, k = t % KP; float a = 0.f;
        if (k < KK) {
            #pragma unroll
            for (int d = 0; d < 32; ++d) a += wo[c * 32 + d] * s_WoT2[d * KP + k];
        }
        s_Wo2[t] = a;
    }
    __syncthreads();

    // -------- Stage 2: BK, BV, P --------
    if (t < 608) {
        int k = t >> 5, c = t & 31;
        float ak = 0.f, av = 0.f;
        #pragma unroll
        for (int d = 0; d < 32; ++d) {
            float b = s_base[k * 32 + d];
            ak += b * wk[d * 32 + c];
            av += b * wv[d * 32 + c];
        }
        s_BK[t] = ak; s_BV[t] = av;
    }
    if (t >= 608 && t < 688) {
        int j = (t - 608) / KP, k = (t - 608) % KP;
        float a = 0.f;
        if (k < KK) {
            if (j < 3) {
                #pragma unroll
                for (int c = 0; c < 32; ++c) a += s_sV[j * 32 + c] * s_Wo2[c * KP + k];
            } else {
                #pragma unroll
                for (int c = 0; c < 32; ++c) a += bv[c] * s_Wo2[c * KP + k];
                #pragma unroll
                for (int d = 0; d < 32; ++d) a += bo[d] * s_WoT2[d * KP + k];
            }
        }
        g_buf[SP + j * KP + k] = a;
    }
    __syncthreads();

    // -------- Stage 3: M1, M2, cM1, cM2, G --------
    if (t < 640) {
        int d = t / KP, k = t % KP; float a = 0.f;
        if (k < KK) {
            #pragma unroll
            for (int c = 0; c < 32; ++c) a += wq[d * 32 + c] * s_BK[k * 32 + c];
        }
        g_buf[SFB + d * 44 + k] = a * rsC;
    } else if (t < 768) {
        int d = (t - 640) / 4, j = (t - 640) % 4; float a = 0.f;
        if (j < 3) {
            #pragma unroll
            for (int c = 0; c < 32; ++c) a += wq[d * 32 + c] * s_sK[j * 32 + c];
        } else {
            #pragma unroll
            for (int c = 0; c < 32; ++c) a += wq[d * 32 + c] * bk[c];
        }
        g_buf[SFB + d * 44 + 20 + j] = a * rsC;
    } else if (t < 788) {
        int k = t - 768; float a = 0.f;
        if (k < KK) {
            #pragma unroll
            for (int c = 0; c < 32; ++c) a += bq[c] * s_BK[k * 32 + c];
        }
        g_buf[SC1 + k] = a * rsC;
    } else if (t < 792) {
        int j = t - 788; float a = 0.f;
        if (j < 3) {
            #pragma unroll
            for (int c = 0; c < 32; ++c) a += bq[c] * s_sK[j * 32 + c];
        } else {
            #pragma unroll
            for (int c = 0; c < 32; ++c) a += bq[c] * bk[c];
        }
        g_buf[SC2 + j] = a * rsC;
    } else {
        for (int u = t - 792; u < KK * KP; u += 232) {
            int kp = u / KP, k = u % KP; float a = 0.f;
            if (k < KK) {
                #pragma unroll
                for (int c = 0; c < 32; ++c) a += s_BV[kp * 32 + c] * s_Wo2[c * KP + k];
            }
            g_buf[SG + kp * KP + k] = a;
        }
    }
}

// ============================================================================
// Main kernel: one thread per point.
// ============================================================================
__global__ void __launch_bounds__(256, 3) refine_kernel(
    const float* __restrict__ feat,
    const float* __restrict__ sflow,
    const float* __restrict__ cpred,
    float* __restrict__ out,
    int N)
{
    __shared__ __align__(16) float sw[BUF_SZ];
    #pragma unroll 3
    for (int i = threadIdx.x; i < BUF_SZ / 4; i += 256)
        reinterpret_cast<float4*>(sw)[i] = reinterpret_cast<const float4*>(g_buf)[i];
    __syncthreads();

    const int n = blockIdx.x * 256 + threadIdx.x;
    if (n >= N) return;

    // ---- feat row, scene_flow ----
    float f[32];
    {
        const float4* fp = reinterpret_cast<const float4*>(feat + (size_t)n * 32);
        #pragma unroll
        for (int i = 0; i < 8; ++i) {
            float4 v = fp[i];
            f[4 * i] = v.x; f[4 * i + 1] = v.y; f[4 * i + 2] = v.z; f[4 * i + 3] = v.w;
        }
    }
    const float* sfp = sflow + (size_t)n * 3;
    const float s0 = sfp[0], s1 = sfp[1], s2v = sfp[2];

    // ---- selection score: h = relu(f@W1f + b1f); score = sigmoid(h@w2 + b2) ----
    float vf;
    {
        u64 h[16];
        #pragma unroll
        for (int i = 0; i < 16; ++i) h[i] = 0ull;
        #pragma unroll
        for (int d = 0; d < 32; ++d) {
            u64 fd2 = pack2(f[d], f[d]);
            const ulonglong2* w = reinterpret_cast<const ulonglong2*>(sw + SW1 + d * 32);
            #pragma unroll
            for (int i = 0; i < 8; ++i) {
                ulonglong2 ww = w[i];
                h[2 * i]     = ffma2(ww.x, fd2, h[2 * i]);
                h[2 * i + 1] = ffma2(ww.y, fd2, h[2 * i + 1]);
            }
        }
        float slin = sw[SB2];
        #pragma unroll
        for (int i = 0; i < 16; ++i) {
            float a, b; unpack2(h[i], a, b);
            a = fmaxf(a + sw[SB1F + 2 * i], 0.f);
            b = fmaxf(b + sw[SB1F + 2 * i + 1], 0.f);
            slin += a * sw[SW2 + 2 * i] + b * sw[SW2 + 2 * i + 1];
        }
        float score = 1.f / (1.f + __expf(-slin));
        bool tmask = (s0 != 0.f) || (s1 != 0.f) || (s2v != 0.f);
        vf = (score < 0.8f && tmask) ? 1.f : 0.f;
    }

    // ---- coarse_pred softmax ----
    float cp[KK];
    {
        const float* cpp = cpred + (size_t)n * KK;
        #pragma unroll
        for (int k = 0; k < KK; ++k) cp[k] = cpp[k];
        float m = cp[0];
        #pragma unroll
        for (int k = 1; k < KK; ++k) m = fmaxf(m, cp[k]);
        float s = 0.f;
        #pragma unroll
        for (int k = 0; k < KK; ++k) { cp[k] = __expf(cp[k] - m); s += cp[k]; }
        float inv = 1.f / s;
        #pragma unroll
        for (int k = 0; k < KK; ++k) cp[k] *= inv;
    }

    // ---- logits: t1[k] = rsC*(q.BK[k]), u = rsC*(q.sK_j, q.bk)  via f@[M1|M2] ----
    float a2[KK]; float s2;
    {
        u64 T[12];
        {
            const u64* c1 = reinterpret_cast<const u64*>(sw + SC1);
            #pragma unroll
            for (int i = 0; i < 10; ++i) T[i] = c1[i];
            const u64* c2 = reinterpret_cast<const u64*>(sw + SC2);
            T[10] = c2[0]; T[11] = c2[1];
        }
        #pragma unroll
        for (int d = 0; d < 32; ++d) {
            u64 fd2 = pack2(f[d], f[d]);
            const ulonglong2* r = reinterpret_cast<const ulonglong2*>(sw + SFB + d * 44);
            #pragma unroll
            for (int i = 0; i < 6; ++i) {
                ulonglong2 ww = r[i];
                T[2 * i]     = ffma2(ww.x, fd2, T[2 * i]);
                T[2 * i + 1] = ffma2(ww.y, fd2, T[2 * i + 1]);
            }
        }
        float t1[20];
        #pragma unroll
        for (int i = 0; i < 10; ++i) unpack2(T[i], t1[2 * i], t1[2 * i + 1]);
        float u0, u1, u2, u3;
        unpack2(T[10], u0, u1); unpack2(T[11], u2, u3);
        float qsK = fmaf(s0, u0, fmaf(s1, u1, s2v * u2));
        float qbk = u3;

        float lg[KK];
        float m = -1e30f;
        #pragma unroll
        for (int k = 0; k < KK; ++k) {
            lg[k] = fmaf(cp[k], t1[k] + qsK, qbk);
            m = fmaxf(m, lg[k]);
        }
        float S = 0.f;
        #pragma unroll
        for (int k = 0; k < KK; ++k) { lg[k] = __expf(lg[k] - m); S += lg[k]; }
        float invS = 1.f / S;
        s2 = 0.f;
        #pragma unroll
        for (int k = 0; k < KK; ++k) { a2[k] = lg[k] * invS * cp[k]; s2 += a2[k]; }
    }

    // ---- out = f@WT1 + bout + vf*( a2@G + s2*(s.P) + P3 ) ----
    {
        u64 O[10];
        {
            const u64* bp = reinterpret_cast<const u64*>(sw + SBOUT);
            #pragma unroll
            for (int i = 0; i < 10; ++i) O[i] = bp[i];
        }
        // rank-4 update from P rows
        float coef[4];
        coef[0] = vf * s2 * s0; coef[1] = vf * s2 * s1; coef[2] = vf * s2 * s2v; coef[3] = vf;
        #pragma unroll
        for (int j = 0; j < 4; ++j) {
            u64 cj2 = pack2(coef[j], coef[j]);
            const ulonglong2* r = reinterpret_cast<const ulonglong2*>(sw + SP + j * KP);
            #pragma unroll
            for (int i = 0; i < 5; ++i) {
                ulonglong2 ww = r[i];
                O[2 * i]     = ffma2(ww.x, cj2, O[2 * i]);
                O[2 * i + 1] = ffma2(ww.y, cj2, O[2 * i + 1]);
            }
        }
        // f @ WT1
        #pragma unroll
        for (int d = 0; d < 32; ++d) {
            u64 fd2 = pack2(f[d], f[d]);
            const ulonglong2* r = reinterpret_cast<const ulonglong2*>(sw + SFB + d * 44 + 24);
            #pragma unroll
            for (int i = 0; i < 5; ++i) {
                ulonglong2 ww = r[i];
                O[2 * i]     = ffma2(ww.x, fd2, O[2 * i]);
                O[2 * i + 1] = ffma2(ww.y, fd2, O[2 * i + 1]);
            }
        }
        // a2 @ G   (a2 already includes softmax*cp; vf folded: scale a2 by vf)
        #pragma unroll
        for (int k = 0; k < KK; ++k) {
            float av = a2[k] * vf;
            u64 ak2 = pack2(av, av);
            const ulonglong2* r = reinterpret_cast<const ulonglong2*>(sw + SG + k * KP);
            #pragma unroll
            for (int i = 0; i < 5; ++i) {
                ulonglong2 ww = r[i];
                O[2 * i]     = ffma2(ww.x, ak2, O[2 * i]);
                O[2 * i + 1] = ffma2(ww.y, ak2, O[2 * i + 1]);
            }
        }
        float o[20];
        #pragma unroll
        for (int i = 0; i < 10; ++i) unpack2(O[i], o[2 * i], o[2 * i + 1]);
        float* op = out + (size_t)n * KK;
        #pragma unroll
        for (int k = 0; k < KK; ++k) op[k] = o[k];
    }
}

// ============================================================================
extern "C" void kernel_launch(void* const* d_in, const int* in_sizes, int n_in,
                              void* d_out, int out_size)
{
    const float* feat      = (const float*)d_in[0];
    const float* sflow     = (const float*)d_in[1];
    const float* cpred     = (const float*)d_in[2];
    const float* z         = (const float*)d_in[3];
    const float* select_w1 = (const float*)d_in[4];
    const float* bn_gamma  = (const float*)d_in[5];
    const float* bn_beta   = (const float*)d_in[6];
    const float* bn_mean   = (const float*)d_in[7];
    const float* bn_var    = (const float*)d_in[8];
    const float* select_w2 = (const float*)d_in[9];
    const float* select_b2 = (const float*)d_in[10];
    const float* wq        = (const float*)d_in[11];
    const float* bq        = (const float*)d_in[12];
    const float* wk        = (const float*)d_in[13];
    const float* bk        = (const float*)d_in[14];
    const float* wv        = (const float*)d_in[15];
    const float* bv        = (const float*)d_in[16];
    const float* wo        = (const float*)d_in[17];
    const float* bo        = (const float*)d_in[18];
    const float* wt        = (const float*)d_in[19];
    const float* bt        = (const float*)d_in[20];
    const float* w_out     = (const float*)d_in[21];
    const float* b_out     = (const float*)d_in[22];
    const float* w_gen     = (const float*)d_in[23];
    const float* b_gen     = (const float*)d_in[24];
    float* out = (float*)d_out;

    const int N = in_sizes[0] / 32;

    setup_kernel<<<1, 1024>>>(z, select_w1, bn_gamma, bn_beta, bn_mean, bn_var,
                              select_w2, select_b2, wq, bq, wk, bk, wv, bv,
                              wo, bo, wt, bt, w_out, b_out, w_gen, b_gen);

    refine_kernel<<<(N + 255) / 256, 256>>>(feat, sflow, cpred, out, N);
}

// round 5
// speedup vs baseline: 1.4372x; 1.1173x over previous
#include <cuda_runtime.h>
#include <math.h>

typedef unsigned long long u64;

#define KK 19
#define KP 20

// ---- folded-constant buffer layout (floats) ----
#define SW1   0      // 1024 [d*32+c] select_w1 * bn_scale
#define SFB   1024   // 1408 [d*44+..] 0..19: M1=rsC*wq@BK^T ; 20..23: M2 ; 24..43: WT1
#define SG    2432   // 400  [k'*20+k] G = BV@Wo2
#define SP    2832   // 80   [j*20+k]  rows 0..2: sV_j@Wo2 ; row 3: bv@Wo2 + bo@WoT2
#define SC1   2912   // 20   cM1
#define SC2   2932   // 4    cM2
#define SBOUT 2936   // 20   b_out + bt@w_out
#define SB1F  2956   // 32   folded BN bias
#define SW2   2988   // 32   select_w2
#define SB2   3020   // 4    select_b2
#define BUF_SZ 3024

__device__ __align__(16) float g_buf[BUF_SZ];

__device__ __forceinline__ u64 ffma2(u64 a, u64 b, u64 c) {
    u64 d; asm("fma.rn.f32x2 %0, %1, %2, %3;" : "=l"(d) : "l"(a), "l"(b), "l"(c)); return d;
}
__device__ __forceinline__ u64 pack2(float x, float y) {
    u64 r; asm("mov.b64 %0, {%1, %2};" : "=l"(r) : "f"(x), "f"(y)); return r;
}
__device__ __forceinline__ void unpack2(u64 v, float& x, float& y) {
    asm("mov.b64 {%0, %1}, %2;" : "=f"(x), "=f"(y) : "l"(v));
}

// ============================================================================
// Setup kernel (unchanged from R4 — verified correct)
// ============================================================================
__global__ void setup_kernel(
    const float* __restrict__ z, const float* __restrict__ select_w1,
    const float* __restrict__ bn_gamma, const float* __restrict__ bn_beta,
    const float* __restrict__ bn_mean, const float* __restrict__ bn_var,
    const float* __restrict__ select_w2, const float* __restrict__ select_b2,
    const float* __restrict__ wq, const float* __restrict__ bq,
    const float* __restrict__ wk, const float* __restrict__ bk,
    const float* __restrict__ wv, const float* __restrict__ bv,
    const float* __restrict__ wo, const float* __restrict__ bo,
    const float* __restrict__ wt, const float* __restrict__ bt,
    const float* __restrict__ w_out, const float* __restrict__ b_out,
    const float* __restrict__ w_gen, const float* __restrict__ b_gen)
{
    __shared__ float s_zw[32];
    __shared__ float s_sK[96], s_sV[96];
    __shared__ float s_WoT2[640], s_Wo2[640];
    __shared__ float s_base[608];
    __shared__ float s_BK[608], s_BV[608];
    const int t = threadIdx.x;
    const float rsC = 0.17677669529663687f;

    {
        int c = t & 31;
        float sc = bn_gamma[c] * rsqrtf(bn_var[c] + 1e-4f);
        g_buf[SW1 + t] = select_w1[t] * sc;
    }
    if (t < 32) {
        float acc = b_gen[t];
        #pragma unroll
        for (int i = 0; i < 16; ++i) acc += z[i] * w_gen[i * 32 + t];
        s_zw[t] = acc;
        float sc = bn_gamma[t] * rsqrtf(bn_var[t] + 1e-4f);
        g_buf[SB1F + t] = bn_beta[t] - bn_mean[t] * sc;
        g_buf[SW2 + t]  = select_w2[t];
    }
    if (t == 32) g_buf[SB2] = select_b2[0];
    if (t < 96) {
        int j = t / 32, c = t % 32;
        float aK = 0.f, aV = 0.f;
        #pragma unroll
        for (int d = 0; d < 32; ++d) {
            float w = w_gen[(35 + j) * 32 + d];
            aK += w * wk[d * 32 + c];
            aV += w * wv[d * 32 + c];
        }
        s_sK[t] = aK; s_sV[t] = aV;
    }
    if (t < 640) {
        int d = t / KP, k = t % KP;
        float a1 = 0.f, a2w = 0.f;
        if (k < KK) {
            #pragma unroll
            for (int e = 0; e < 32; ++e) {
                a1  += wt[d * 32 + e]        * w_out[e * KK + k];
                a2w += wt[(32 + d) * 32 + e] * w_out[e * KK + k];
            }
        }
        g_buf[SFB + d * 44 + 24 + k] = a1;
        s_WoT2[t] = a2w;
    }
    if (t >= 640 && t < 660) {
        int k = t - 640; float a = 0.f;
        if (k < KK) {
            a = b_out[k];
            #pragma unroll
            for (int e = 0; e < 32; ++e) a += bt[e] * w_out[e * KK + k];
        }
        g_buf[SBOUT + k] = a;
    }
    __syncthreads();

    if (t < 608)
        s_base[t] = s_zw[t & 31] + w_gen[(16 + (t >> 5)) * 32 + (t & 31)];
    if (t < 640) {
        int c = t / KP, k = t % KP; float a = 0.f;
        if (k < KK) {
            #pragma unroll
            for (int d = 0; d < 32; ++d) a += wo[c * 32 + d] * s_WoT2[d * KP + k];
        }
        s_Wo2[t] = a;
    }
    __syncthreads();

    if (t < 608) {
        int k = t >> 5, c = t & 31;
        float ak = 0.f, av = 0.f;
        #pragma unroll
        for (int d = 0; d < 32; ++d) {
            float b = s_base[k * 32 + d];
            ak += b * wk[d * 32 + c];
            av += b * wv[d * 32 + c];
        }
        s_BK[t] = ak; s_BV[t] = av;
    }
    if (t >= 608 && t < 688) {
        int j = (t - 608) / KP, k = (t - 608) % KP;
        float a = 0.f;
        if (k < KK) {
            if (j < 3) {
                #pragma unroll
                for (int c = 0; c < 32; ++c) a += s_sV[j * 32 + c] * s_Wo2[c * KP + k];
            } else {
                #pragma unroll
                for (int c = 0; c < 32; ++c) a += bv[c] * s_Wo2[c * KP + k];
                #pragma unroll
                for (int d = 0; d < 32; ++d) a += bo[d] * s_WoT2[d * KP + k];
            }
        }
        g_buf[SP + j * KP + k] = a;
    }
    __syncthreads();

    if (t < 640) {
        int d = t / KP, k = t % KP; float a = 0.f;
        if (k < KK) {
            #pragma unroll
            for (int c = 0; c < 32; ++c) a += wq[d * 32 + c] * s_BK[k * 32 + c];
        }
        g_buf[SFB + d * 44 + k] = a * rsC;
    } else if (t < 768) {
        int d = (t - 640) / 4, j = (t - 640) % 4; float a = 0.f;
        if (j < 3) {
            #pragma unroll
            for (int c = 0; c < 32; ++c) a += wq[d * 32 + c] * s_sK[j * 32 + c];
        } else {
            #pragma unroll
            for (int c = 0; c < 32; ++c) a += wq[d * 32 + c] * bk[c];
        }
        g_buf[SFB + d * 44 + 20 + j] = a * rsC;
    } else if (t < 788) {
        int k = t - 768; float a = 0.f;
        if (k < KK) {
            #pragma unroll
            for (int c = 0; c < 32; ++c) a += bq[c] * s_BK[k * 32 + c];
        }
        g_buf[SC1 + k] = a * rsC;
    } else if (t < 792) {
        int j = t - 788; float a = 0.f;
        if (j < 3) {
            #pragma unroll
            for (int c = 0; c < 32; ++c) a += bq[c] * s_sK[j * 32 + c];
        } else {
            #pragma unroll
            for (int c = 0; c < 32; ++c) a += bq[c] * bk[c];
        }
        g_buf[SC2 + j] = a * rsC;
    } else {
        for (int u = t - 792; u < KK * KP; u += 232) {
            int kp = u / KP, k = u % KP; float a = 0.f;
            if (k < KK) {
                #pragma unroll
                for (int c = 0; c < 32; ++c) a += s_BV[kp * 32 + c] * s_Wo2[c * KP + k];
            }
            g_buf[SG + kp * KP + k] = a;
        }
    }
}

// ============================================================================
// Attention-logit chunk: cols [C0, C0+4*NW), accumulate into m[] / sums.
// ============================================================================
template<int C0, int NW>
__device__ __forceinline__ void t_chunk(
    const float* sw, const float* fA, const float* fB,
    const float* cpA, const float* cpB,
    float qsKA, float qbkA, float qsKB, float qbkB,
    float* mA, float* mB,
    float& SeA, float& SmA, float& SeB, float& SmB)
{
    u64 TA[2 * NW], TB[2 * NW];
    const u64* c1 = reinterpret_cast<const u64*>(sw + SC1);
    #pragma unroll
    for (int i = 0; i < 2 * NW; ++i) { TA[i] = c1[C0 / 2 + i]; TB[i] = TA[i]; }
    #pragma unroll
    for (int d = 0; d < 32; ++d) {
        const ulonglong2* r = reinterpret_cast<const ulonglong2*>(sw + SFB + d * 44 + C0);
        u64 fa = pack2(fA[d], fA[d]);
        u64 fb = pack2(fB[d], fB[d]);
        #pragma unroll
        for (int i = 0; i < NW; ++i) {
            ulonglong2 ww = r[i];
            TA[2 * i]     = ffma2(ww.x, fa, TA[2 * i]);
            TA[2 * i + 1] = ffma2(ww.y, fa, TA[2 * i + 1]);
            TB[2 * i]     = ffma2(ww.x, fb, TB[2 * i]);
            TB[2 * i + 1] = ffma2(ww.y, fb, TB[2 * i + 1]);
        }
    }
    #pragma unroll
    for (int i = 0; i < 2 * NW; ++i) {
        const int k0 = C0 + 2 * i, k1 = k0 + 1;
        float tx, ty;
        unpack2(TA[i], tx, ty);
        if (k0 < KK) { float el = __expf(fmaf(cpA[k0], tx + qsKA, qbkA)); SeA += el; mA[k0] = el * cpA[k0]; SmA += mA[k0]; }
        if (k1 < KK) { float el = __expf(fmaf(cpA[k1], ty + qsKA, qbkA)); SeA += el; mA[k1] = el * cpA[k1]; SmA += mA[k1]; }
        unpack2(TB[i], tx, ty);
        if (k0 < KK) { float el = __expf(fmaf(cpB[k0], tx + qsKB, qbkB)); SeB += el; mB[k0] = el * cpB[k0]; SmB += mB[k0]; }
        if (k1 < KK) { float el = __expf(fmaf(cpB[k1], ty + qsKB, qbkB)); SeB += el; mB[k1] = el * cpB[k1]; SmB += mB[k1]; }
    }
}

// ============================================================================
// Main kernel: TWO points per thread (weights LDS shared between both).
// ============================================================================
__global__ void __launch_bounds__(128, 4) refine_kernel(
    const float* __restrict__ feat,
    const float* __restrict__ sflow,
    const float* __restrict__ cpred,
    float* __restrict__ out,
    int N)
{
    __shared__ __align__(16) float sw[BUF_SZ];
    #pragma unroll
    for (int i = threadIdx.x; i < BUF_SZ / 4; i += 128)
        reinterpret_cast<float4*>(sw)[i] = reinterpret_cast<const float4*>(g_buf)[i];
    __syncthreads();

    const int p = blockIdx.x * 128 + threadIdx.x;
    const int nA = 2 * p;
    if (nA >= N) return;
    const bool pair = (nA + 1 < N);
    const int nB = pair ? nA + 1 : nA;

    // ---- features (scalar regs; packed on the fly) ----
    float fA[32], fB[32];
    {
        const float4* fp = reinterpret_cast<const float4*>(feat + (size_t)nA * 32);
        #pragma unroll
        for (int i = 0; i < 8; ++i) {
            float4 v = fp[i];
            fA[4 * i] = v.x; fA[4 * i + 1] = v.y; fA[4 * i + 2] = v.z; fA[4 * i + 3] = v.w;
        }
        fp = reinterpret_cast<const float4*>(feat + (size_t)nB * 32);
        #pragma unroll
        for (int i = 0; i < 8; ++i) {
            float4 v = fp[i];
            fB[4 * i] = v.x; fB[4 * i + 1] = v.y; fB[4 * i + 2] = v.z; fB[4 * i + 3] = v.w;
        }
    }
    const float* sa = sflow + (size_t)nA * 3;
    const float* sb = sflow + (size_t)nB * 3;
    const float sA0 = sa[0], sA1 = sa[1], sA2 = sa[2];
    const float sB0 = sb[0], sB1 = sb[1], sB2 = sb[2];

    // ---- selection score (two column-halves to bound regs) ----
    float vfA, vfB;
    {
        float slinA = sw[SB2], slinB = slinA;
        #pragma unroll
        for (int half = 0; half < 2; ++half) {
            u64 hA[8], hB[8];
            #pragma unroll
            for (int i = 0; i < 8; ++i) { hA[i] = 0ull; hB[i] = 0ull; }
            #pragma unroll
            for (int d = 0; d < 32; ++d) {
                const ulonglong2* w = reinterpret_cast<const ulonglong2*>(sw + SW1 + d * 32 + half * 16);
                u64 fa = pack2(fA[d], fA[d]);
                u64 fb = pack2(fB[d], fB[d]);
                #pragma unroll
                for (int i = 0; i < 4; ++i) {
                    ulonglong2 ww = w[i];
                    hA[2 * i]     = ffma2(ww.x, fa, hA[2 * i]);
                    hA[2 * i + 1] = ffma2(ww.y, fa, hA[2 * i + 1]);
                    hB[2 * i]     = ffma2(ww.x, fb, hB[2 * i]);
                    hB[2 * i + 1] = ffma2(ww.y, fb, hB[2 * i + 1]);
                }
            }
            #pragma unroll
            for (int i = 0; i < 8; ++i) {
                float bx = sw[SB1F + half * 16 + 2 * i], by = sw[SB1F + half * 16 + 2 * i + 1];
                float wx = sw[SW2  + half * 16 + 2 * i], wy = sw[SW2  + half * 16 + 2 * i + 1];
                float x, y;
                unpack2(hA[i], x, y);
                slinA += fmaxf(x + bx, 0.f) * wx + fmaxf(y + by, 0.f) * wy;
                unpack2(hB[i], x, y);
                slinB += fmaxf(x + bx, 0.f) * wx + fmaxf(y + by, 0.f) * wy;
            }
        }
        const float thr = 1.3862943611198906f;   // ln(4): sigmoid(s) < 0.8  <=>  s < ln4
        bool mAv = (sA0 != 0.f) || (sA1 != 0.f) || (sA2 != 0.f);
        bool mBv = (sB0 != 0.f) || (sB1 != 0.f) || (sB2 != 0.f);
        vfA = (slinA < thr && mAv) ? 1.f : 0.f;
        vfB = (slinB < thr && mBv) ? 1.f : 0.f;
    }

    // ---- coarse_pred softmax (no max shift; logits are O(5)) ----
    float cpA[KK], cpB[KK];
    {
        if (pair) {
            const float2* c2 = reinterpret_cast<const float2*>(cpred + (size_t)nA * KK);
            #pragma unroll
            for (int j = 0; j < 19; ++j) {
                float2 v = c2[j];
                const int i0 = 2 * j, i1 = 2 * j + 1;
                if (i0 < KK) cpA[i0] = v.x; else cpB[i0 - KK] = v.x;
                if (i1 < KK) cpA[i1] = v.y; else cpB[i1 - KK] = v.y;
            }
        } else {
            const float* c = cpred + (size_t)nA * KK;
            #pragma unroll
            for (int k = 0; k < KK; ++k) { cpA[k] = c[k]; cpB[k] = cpA[k]; }
        }
        float SA = 0.f, SB = 0.f;
        #pragma unroll
        for (int k = 0; k < KK; ++k) {
            cpA[k] = __expf(cpA[k]); SA += cpA[k];
            cpB[k] = __expf(cpB[k]); SB += cpB[k];
        }
        float iA = 1.f / SA, iB = 1.f / SB;
        #pragma unroll
        for (int k = 0; k < KK; ++k) { cpA[k] *= iA; cpB[k] *= iB; }
    }

    // ---- u-cols: qsK, qbk ----
    float qsKA, qbkA, qsKB, qbkB;
    {
        const u64* c2 = reinterpret_cast<const u64*>(sw + SC2);
        u64 uA0 = c2[0], uA1 = c2[1], uB0 = uA0, uB1 = uA1;
        #pragma unroll
        for (int d = 0; d < 32; ++d) {
            ulonglong2 ww = *reinterpret_cast<const ulonglong2*>(sw + SFB + d * 44 + 20);
            u64 fa = pack2(fA[d], fA[d]);
            u64 fb = pack2(fB[d], fB[d]);
            uA0 = ffma2(ww.x, fa, uA0); uA1 = ffma2(ww.y, fa, uA1);
            uB0 = ffma2(ww.x, fb, uB0); uB1 = ffma2(ww.y, fb, uB1);
        }
        float a, b, c, d2;
        unpack2(uA0, a, b); unpack2(uA1, c, d2);
        qsKA = fmaf(sA0, a, fmaf(sA1, b, sA2 * c)); qbkA = d2;
        unpack2(uB0, a, b); unpack2(uB1, c, d2);
        qsKB = fmaf(sB0, a, fmaf(sB1, b, sB2 * c)); qbkB = d2;
    }

    // ---- attention logits -> m[] (cp consumed in place), sums ----
    float mA[KK], mB[KK];
    float SeA = 0.f, SmA = 0.f, SeB = 0.f, SmB = 0.f;
    t_chunk<0, 2>(sw, fA, fB, cpA, cpB, qsKA, qbkA, qsKB, qbkB, mA, mB, SeA, SmA, SeB, SmB);
    t_chunk<8, 2>(sw, fA, fB, cpA, cpB, qsKA, qbkA, qsKB, qbkB, mA, mB, SeA, SmA, SeB, SmB);
    t_chunk<16, 1>(sw, fA, fB, cpA, cpB, qsKA, qbkA, qsKB, qbkB, mA, mB, SeA, SmA, SeB, SmB);

    const float invA = 1.f / SeA, invB = 1.f / SeB;
    const float gA = vfA * invA, gB = vfB * invB;
    const float s2A = SmA * invA, s2B = SmB * invB;

    // ---- output accumulation ----
    u64 OA[10], OB[10];
    {
        const u64* bp = reinterpret_cast<const u64*>(sw + SBOUT);
        #pragma unroll
        for (int i = 0; i < 10; ++i) { OA[i] = bp[i]; OB[i] = bp[i]; }
    }
    // a2 @ G   (m dies here)
    #pragma unroll
    for (int k = 0; k < KK; ++k) {
        float avA = mA[k] * gA, avB = mB[k] * gB;
        u64 aA = pack2(avA, avA), aB = pack2(avB, avB);
        const ulonglong2* r = reinterpret_cast<const ulonglong2*>(sw + SG + k * KP);
        #pragma unroll
        for (int i = 0; i < 5; ++i) {
            ulonglong2 ww = r[i];
            OA[2 * i]     = ffma2(ww.x, aA, OA[2 * i]);
            OA[2 * i + 1] = ffma2(ww.y, aA, OA[2 * i + 1]);
            OB[2 * i]     = ffma2(ww.x, aB, OB[2 * i]);
            OB[2 * i + 1] = ffma2(ww.y, aB, OB[2 * i + 1]);
        }
    }
    // rank-4 update
    {
        float cAr[4] = { vfA * s2A * sA0, vfA * s2A * sA1, vfA * s2A * sA2, vfA };
        float cBr[4] = { vfB * s2B * sB0, vfB * s2B * sB1, vfB * s2B * sB2, vfB };
        #pragma unroll
        for (int j = 0; j < 4; ++j) {
            u64 aA = pack2(cAr[j], cAr[j]), aB = pack2(cBr[j], cBr[j]);
            const ulonglong2* r = reinterpret_cast<const ulonglong2*>(sw + SP + j * KP);
            #pragma unroll
            for (int i = 0; i < 5; ++i) {
                ulonglong2 ww = r[i];
                OA[2 * i]     = ffma2(ww.x, aA, OA[2 * i]);
                OA[2 * i + 1] = ffma2(ww.y, aA, OA[2 * i + 1]);
                OB[2 * i]     = ffma2(ww.x, aB, OB[2 * i]);
                OB[2 * i + 1] = ffma2(ww.y, aB, OB[2 * i + 1]);
            }
        }
    }
    // f @ WT1
    #pragma unroll
    for (int d = 0; d < 32; ++d) {
        u64 fa = pack2(fA[d], fA[d]);
        u64 fb = pack2(fB[d], fB[d]);
        const ulonglong2* r = reinterpret_cast<const ulonglong2*>(sw + SFB + d * 44 + 24);
        #pragma unroll
        for (int i = 0; i < 5; ++i) {
            ulonglong2 ww = r[i];
            OA[2 * i]     = ffma2(ww.x, fa, OA[2 * i]);
            OA[2 * i + 1] = ffma2(ww.y, fa, OA[2 * i + 1]);
            OB[2 * i]     = ffma2(ww.x, fb, OB[2 * i]);
            OB[2 * i + 1] = ffma2(ww.y, fb, OB[2 * i + 1]);
        }
    }

    // ---- store ----
    float oA[20], oB[20];
    #pragma unroll
    for (int i = 0; i < 10; ++i) {
        unpack2(OA[i], oA[2 * i], oA[2 * i + 1]);
        unpack2(OB[i], oB[2 * i], oB[2 * i + 1]);
    }
    if (pair) {
        float2* op2 = reinterpret_cast<float2*>(out + (size_t)nA * KK);
        #pragma unroll
        for (int j = 0; j < 19; ++j) {
            float2 v;
            v.x = (2 * j     < KK) ? oA[2 * j]     : oB[2 * j - KK];
            v.y = (2 * j + 1 < KK) ? oA[2 * j + 1] : oB[2 * j + 1 - KK];
            op2[j] = v;
        }
    } else {
        float* op = out + (size_t)nA * KK;
        #pragma unroll
        for (int k = 0; k < KK; ++k) op[k] = oA[k];
    }
}

// ============================================================================
extern "C" void kernel_launch(void* const* d_in, const int* in_sizes, int n_in,
                              void* d_out, int out_size)
{
    const float* feat      = (const float*)d_in[0];
    const float* sflow     = (const float*)d_in[1];
    const float* cpred     = (const float*)d_in[2];
    const float* z         = (const float*)d_in[3];
    const float* select_w1 = (const float*)d_in[4];
    const float* bn_gamma  = (const float*)d_in[5];
    const float* bn_beta   = (const float*)d_in[6];
    const float* bn_mean   = (const float*)d_in[7];
    const float* bn_var    = (const float*)d_in[8];
    const float* select_w2 = (const float*)d_in[9];
    const float* select_b2 = (const float*)d_in[10];
    const float* wq        = (const float*)d_in[11];
    const float* bq        = (const float*)d_in[12];
    const float* wk        = (const float*)d_in[13];
    const float* bk        = (const float*)d_in[14];
    const float* wv        = (const float*)d_in[15];
    const float* bv        = (const float*)d_in[16];
    const float* wo        = (const float*)d_in[17];
    const float* bo        = (const float*)d_in[18];
    const float* wt        = (const float*)d_in[19];
    const float* bt        = (const float*)d_in[20];
    const float* w_out     = (const float*)d_in[21];
    const float* b_out     = (const float*)d_in[22];
    const float* w_gen     = (const float*)d_in[23];
    const float* b_gen     = (const float*)d_in[24];
    float* out = (float*)d_out;

    const int N = in_sizes[0] / 32;

    setup_kernel<<<1, 1024>>>(z, select_w1, bn_gamma, bn_beta, bn_mean, bn_var,
                              select_w2, select_b2, wq, bq, wk, bk, wv, bv,
                              wo, bo, wt, bt, w_out, b_out, w_gen, b_gen);

    const int pairs = (N + 1) / 2;
    refine_kernel<<<(pairs + 127) / 128, 128>>>(feat, sflow, cpred, out, N);
}

// round 6
// speedup vs baseline: 1.4455x; 1.0058x over previous
#include <cuda_runtime.h>
#include <math.h>

typedef unsigned long long u64;

#define KK 19
#define KP 20

// ---- folded-constant buffer layout (floats) ----
#define SW1   0      // 1024 [d*32+c] select_w1 * bn_scale
#define SFB   1024   // 1408 [d*44+..] 0..19: M1=rsC*wq@BK^T ; 20..23: M2 ; 24..43: WT1
#define SG    2432   // 400  [k'*20+k] G = BV@Wo2
#define SP    2832   // 80   [j*20+k]  rows 0..2: sV_j@Wo2 ; row 3: bv@Wo2 + bo@WoT2
#define SC1   2912   // 20   cM1
#define SC2   2932   // 4    cM2
#define SBOUT 2936   // 20   b_out + bt@w_out
#define SB1F  2956   // 32   folded BN bias
#define SW2   2988   // 32   select_w2
#define SB2   3020   // 4    select_b2
#define BUF_SZ 3024

__device__ __align__(16) float g_buf[BUF_SZ];

__device__ __forceinline__ u64 ffma2(u64 a, u64 b, u64 c) {
    u64 d; asm("fma.rn.f32x2 %0, %1, %2, %3;" : "=l"(d) : "l"(a), "l"(b), "l"(c)); return d;
}
__device__ __forceinline__ u64 pack2(float x, float y) {
    u64 r; asm("mov.b64 %0, {%1, %2};" : "=l"(r) : "f"(x), "f"(y)); return r;
}
__device__ __forceinline__ void unpack2(u64 v, float& x, float& y) {
    asm("mov.b64 {%0, %1}, %2;" : "=f"(x), "=f"(y) : "l"(v));
}

// ============================================================================
// Setup kernel: fold all weights. 1 block, 1024 threads.
// ============================================================================
__global__ void setup_kernel(
    const float* __restrict__ z, const float* __restrict__ select_w1,
    const float* __restrict__ bn_gamma, const float* __restrict__ bn_beta,
    const float* __restrict__ bn_mean, const float* __restrict__ bn_var,
    const float* __restrict__ select_w2, const float* __restrict__ select_b2,
    const float* __restrict__ wq, const float* __restrict__ bq,
    const float* __restrict__ wk, const float* __restrict__ bk,
    const float* __restrict__ wv, const float* __restrict__ bv,
    const float* __restrict__ wo, const float* __restrict__ bo,
    const float* __restrict__ wt, const float* __restrict__ bt,
    const float* __restrict__ w_out, const float* __restrict__ b_out,
    const float* __restrict__ w_gen, const float* __restrict__ b_gen)
{
    __shared__ float s_zw[32];
    __shared__ float s_sK[96], s_sV[96];
    __shared__ float s_WoT2[640], s_Wo2[640];
    __shared__ float s_base[608];
    __shared__ float s_BK[608], s_BV[608];
    __shared__ float s_wq[1024], s_wo[1024];
    const int t = threadIdx.x;
    const float rsC = 0.17677669529663687f;

    // prefetch later-stage matrices into smem (hide cold-gmem latency)
    s_wq[t] = wq[t];
    s_wo[t] = wo[t];

    {
        int c = t & 31;
        float sc = bn_gamma[c] * rsqrtf(bn_var[c] + 1e-4f);
        g_buf[SW1 + t] = select_w1[t] * sc;
    }
    if (t < 32) {
        float acc = b_gen[t];
        #pragma unroll
        for (int i = 0; i < 16; ++i) acc += z[i] * w_gen[i * 32 + t];
        s_zw[t] = acc;
        float sc = bn_gamma[t] * rsqrtf(bn_var[t] + 1e-4f);
        g_buf[SB1F + t] = bn_beta[t] - bn_mean[t] * sc;
        g_buf[SW2 + t]  = select_w2[t];
    }
    if (t == 32) g_buf[SB2] = select_b2[0];
    if (t < 96) {
        int j = t / 32, c = t % 32;
        float aK = 0.f, aV = 0.f;
        #pragma unroll
        for (int d = 0; d < 32; ++d) {
            float w = w_gen[(35 + j) * 32 + d];
            aK += w * wk[d * 32 + c];
            aV += w * wv[d * 32 + c];
        }
        s_sK[t] = aK; s_sV[t] = aV;
    }
    if (t < 640) {
        int d = t / KP, k = t % KP;
        float a1 = 0.f, a2w = 0.f;
        if (k < KK) {
            #pragma unroll
            for (int e = 0; e < 32; ++e) {
                a1  += wt[d * 32 + e]        * w_out[e * KK + k];
                a2w += wt[(32 + d) * 32 + e] * w_out[e * KK + k];
            }
        }
        g_buf[SFB + d * 44 + 24 + k] = a1;
        s_WoT2[t] = a2w;
    }
    if (t >= 640 && t < 660) {
        int k = t - 640; float a = 0.f;
        if (k < KK) {
            a = b_out[k];
            #pragma unroll
            for (int e = 0; e < 32; ++e) a += bt[e] * w_out[e * KK + k];
        }
        g_buf[SBOUT + k] = a;
    }
    __syncthreads();

    if (t < 608)
        s_base[t] = s_zw[t & 31] + w_gen[(16 + (t >> 5)) * 32 + (t & 31)];
    if (t < 640) {
        int c = t / KP, k = t % KP; float a = 0.f;
        if (k < KK) {
            #pragma unroll
            for (int d = 0; d < 32; ++d) a += s_wo[c * 32 + d] * s_WoT2[d * KP + k];
        }
        s_Wo2[t] = a;
    }
    __syncthreads();

    if (t < 608) {
        int k = t >> 5, c = t & 31;
        float ak = 0.f, av = 0.f;
        #pragma unroll
        for (int d = 0; d < 32; ++d) {
            float b = s_base[k * 32 + d];
            ak += b * wk[d * 32 + c];
            av += b * wv[d * 32 + c];
        }
        s_BK[t] = ak; s_BV[t] = av;
    }
    if (t >= 608 && t < 688) {
        int j = (t - 608) / KP, k = (t - 608) % KP;
        float a = 0.f;
        if (k < KK) {
            if (j < 3) {
                #pragma unroll
                for (int c = 0; c < 32; ++c) a += s_sV[j * 32 + c] * s_Wo2[c * KP + k];
            } else {
                #pragma unroll
                for (int c = 0; c < 32; ++c) a += bv[c] * s_Wo2[c * KP + k];
                #pragma unroll
                for (int d = 0; d < 32; ++d) a += bo[d] * s_WoT2[d * KP + k];
            }
        }
        g_buf[SP + j * KP + k] = a;
    }
    __syncthreads();

    if (t < 640) {
        int d = t / KP, k = t % KP; float a = 0.f;
        if (k < KK) {
            #pragma unroll
            for (int c = 0; c < 32; ++c) a += s_wq[d * 32 + c] * s_BK[k * 32 + c];
        }
        g_buf[SFB + d * 44 + k] = a * rsC;
    } else if (t < 768) {
        int d = (t - 640) / 4, j = (t - 640) % 4; float a = 0.f;
        if (j < 3) {
            #pragma unroll
            for (int c = 0; c < 32; ++c) a += s_wq[d * 32 + c] * s_sK[j * 32 + c];
        } else {
            #pragma unroll
            for (int c = 0; c < 32; ++c) a += s_wq[d * 32 + c] * bk[c];
        }
        g_buf[SFB + d * 44 + 20 + j] = a * rsC;
    } else if (t < 788) {
        int k = t - 768; float a = 0.f;
        if (k < KK) {
            #pragma unroll
            for (int c = 0; c < 32; ++c) a += bq[c] * s_BK[k * 32 + c];
        }
        g_buf[SC1 + k] = a * rsC;
    } else if (t < 792) {
        int j = t - 788; float a = 0.f;
        if (j < 3) {
            #pragma unroll
            for (int c = 0; c < 32; ++c) a += bq[c] * s_sK[j * 32 + c];
        } else {
            #pragma unroll
            for (int c = 0; c < 32; ++c) a += bq[c] * bk[c];
        }
        g_buf[SC2 + j] = a * rsC;
    } else {
        for (int u = t - 792; u < KK * KP; u += 232) {
            int kp = u / KP, k = u % KP; float a = 0.f;
            if (k < KK) {
                #pragma unroll
                for (int c = 0; c < 32; ++c) a += s_BV[kp * 32 + c] * s_Wo2[c * KP + k];
            }
            g_buf[SG + kp * KP + k] = a;
        }
    }
}

// ============================================================================
// Attention-logit chunk: cols [C0, C0+4*NW). IN-PLACE: cp[k] <- exp(lg)*cp[k].
// ============================================================================
template<int C0, int NW>
__device__ __forceinline__ void t_chunk(
    const float* sw, const float* fA, const float* fB,
    float* cpA, float* cpB,
    float qsKA, float qbkA, float qsKB, float qbkB,
    float& SeA, float& SmA, float& SeB, float& SmB)
{
    u64 TA[2 * NW], TB[2 * NW];
    const u64* c1 = reinterpret_cast<const u64*>(sw + SC1);
    #pragma unroll
    for (int i = 0; i < 2 * NW; ++i) { TA[i] = c1[C0 / 2 + i]; TB[i] = TA[i]; }
    #pragma unroll
    for (int d = 0; d < 32; ++d) {
        const ulonglong2* r = reinterpret_cast<const ulonglong2*>(sw + SFB + d * 44 + C0);
        u64 fa = pack2(fA[d], fA[d]);
        u64 fb = pack2(fB[d], fB[d]);
        #pragma unroll
        for (int i = 0; i < NW; ++i) {
            ulonglong2 ww = r[i];
            TA[2 * i]     = ffma2(ww.x, fa, TA[2 * i]);
            TA[2 * i + 1] = ffma2(ww.y, fa, TA[2 * i + 1]);
            TB[2 * i]     = ffma2(ww.x, fb, TB[2 * i]);
            TB[2 * i + 1] = ffma2(ww.y, fb, TB[2 * i + 1]);
        }
    }
    #pragma unroll
    for (int i = 0; i < 2 * NW; ++i) {
        const int k0 = C0 + 2 * i, k1 = k0 + 1;
        float tx, ty;
        unpack2(TA[i], tx, ty);
        if (k0 < KK) { float el = __expf(fmaf(cpA[k0], tx + qsKA, qbkA)); SeA += el; cpA[k0] *= el; SmA += cpA[k0]; }
        if (k1 < KK) { float el = __expf(fmaf(cpA[k1], ty + qsKA, qbkA)); SeA += el; cpA[k1] *= el; SmA += cpA[k1]; }
        unpack2(TB[i], tx, ty);
        if (k0 < KK) { float el = __expf(fmaf(cpB[k0], tx + qsKB, qbkB)); SeB += el; cpB[k0] *= el; SmB += cpB[k0]; }
        if (k1 < KK) { float el = __expf(fmaf(cpB[k1], ty + qsKB, qbkB)); SeB += el; cpB[k1] *= el; SmB += cpB[k1]; }
    }
}

// ============================================================================
// Main kernel: TWO points per thread, 64-thread blocks, 8 CTAs/SM.
// ============================================================================
__global__ void __launch_bounds__(64, 8) refine_kernel(
    const float* __restrict__ feat,
    const float* __restrict__ sflow,
    const float* __restrict__ cpred,
    float* __restrict__ out,
    int N)
{
    __shared__ __align__(16) float sw[BUF_SZ];
    for (int i = threadIdx.x; i < BUF_SZ / 4; i += 64)
        reinterpret_cast<float4*>(sw)[i] = reinterpret_cast<const float4*>(g_buf)[i];
    __syncthreads();

    const int p = blockIdx.x * 64 + threadIdx.x;
    const int nA = 2 * p;
    if (nA >= N) return;
    const bool pair = (nA + 1 < N);
    const int nB = pair ? nA + 1 : nA;

    const float* sa = sflow + (size_t)nA * 3;
    const float* sb = sflow + (size_t)nB * 3;
    const float sA0 = sa[0], sA1 = sa[1], sA2 = sa[2];
    const float sB0 = sb[0], sB1 = sb[1], sB2 = sb[2];

    // ================= PHASE A: everything that needs f resident =========
    float fA[32], fB[32];
    {
        const float4* fp = reinterpret_cast<const float4*>(feat + (size_t)nA * 32);
        #pragma unroll
        for (int i = 0; i < 8; ++i) {
            float4 v = fp[i];
            fA[4 * i] = v.x; fA[4 * i + 1] = v.y; fA[4 * i + 2] = v.z; fA[4 * i + 3] = v.w;
        }
        fp = reinterpret_cast<const float4*>(feat + (size_t)nB * 32);
        #pragma unroll
        for (int i = 0; i < 8; ++i) {
            float4 v = fp[i];
            fB[4 * i] = v.x; fB[4 * i + 1] = v.y; fB[4 * i + 2] = v.z; fB[4 * i + 3] = v.w;
        }
    }

    // ---- selection score (two halves to bound temp regs) ----
    float vfA, vfB;
    {
        float slinA = sw[SB2], slinB = slinA;
        #pragma unroll
        for (int half = 0; half < 2; ++half) {
            u64 hA[8], hB[8];
            #pragma unroll
            for (int i = 0; i < 8; ++i) { hA[i] = 0ull; hB[i] = 0ull; }
            #pragma unroll
            for (int d = 0; d < 32; ++d) {
                const ulonglong2* w = reinterpret_cast<const ulonglong2*>(sw + SW1 + d * 32 + half * 16);
                u64 fa = pack2(fA[d], fA[d]);
                u64 fb = pack2(fB[d], fB[d]);
                #pragma unroll
                for (int i = 0; i < 4; ++i) {
                    ulonglong2 ww = w[i];
                    hA[2 * i]     = ffma2(ww.x, fa, hA[2 * i]);
                    hA[2 * i + 1] = ffma2(ww.y, fa, hA[2 * i + 1]);
                    hB[2 * i]     = ffma2(ww.x, fb, hB[2 * i]);
                    hB[2 * i + 1] = ffma2(ww.y, fb, hB[2 * i + 1]);
                }
            }
            #pragma unroll
            for (int i = 0; i < 8; ++i) {
                float bx = sw[SB1F + half * 16 + 2 * i], by = sw[SB1F + half * 16 + 2 * i + 1];
                float wx = sw[SW2  + half * 16 + 2 * i], wy = sw[SW2  + half * 16 + 2 * i + 1];
                float x, y;
                unpack2(hA[i], x, y);
                slinA += fmaxf(x + bx, 0.f) * wx + fmaxf(y + by, 0.f) * wy;
                unpack2(hB[i], x, y);
                slinB += fmaxf(x + bx, 0.f) * wx + fmaxf(y + by, 0.f) * wy;
            }
        }
        const float thr = 1.3862943611198906f;   // ln(4): sigmoid(s)<0.8 <=> s<ln4
        bool mAv = (sA0 != 0.f) || (sA1 != 0.f) || (sA2 != 0.f);
        bool mBv = (sB0 != 0.f) || (sB1 != 0.f) || (sB2 != 0.f);
        vfA = (slinA < thr && mAv) ? 1.f : 0.f;
        vfB = (slinB < thr && mBv) ? 1.f : 0.f;
    }

    // ---- u-cols: qsK, qbk ----
    float qsKA, qbkA, qsKB, qbkB;
    {
        const u64* c2 = reinterpret_cast<const u64*>(sw + SC2);
        u64 uA0 = c2[0], uA1 = c2[1], uB0 = uA0, uB1 = uA1;
        #pragma unroll
        for (int d = 0; d < 32; ++d) {
            ulonglong2 ww = *reinterpret_cast<const ulonglong2*>(sw + SFB + d * 44 + 20);
            u64 fa = pack2(fA[d], fA[d]);
            u64 fb = pack2(fB[d], fB[d]);
            uA0 = ffma2(ww.x, fa, uA0); uA1 = ffma2(ww.y, fa, uA1);
            uB0 = ffma2(ww.x, fb, uB0); uB1 = ffma2(ww.y, fb, uB1);
        }
        float a, b, c, d2;
        unpack2(uA0, a, b); unpack2(uA1, c, d2);
        qsKA = fmaf(sA0, a, fmaf(sA1, b, sA2 * c)); qbkA = d2;
        unpack2(uB0, a, b); unpack2(uB1, c, d2);
        qsKB = fmaf(sB0, a, fmaf(sB1, b, sB2 * c)); qbkB = d2;
    }

    // ---- coarse_pred softmax ----
    float cpA[KK], cpB[KK];
    {
        if (pair) {
            const float2* c2 = reinterpret_cast<const float2*>(cpred + (size_t)nA * KK);
            #pragma unroll
            for (int j = 0; j < 19; ++j) {
                float2 v = c2[j];
                const int i0 = 2 * j, i1 = 2 * j + 1;
                if (i0 < KK) cpA[i0] = v.x; else cpB[i0 - KK] = v.x;
                if (i1 < KK) cpA[i1] = v.y; else cpB[i1 - KK] = v.y;
            }
        } else {
            const float* c = cpred + (size_t)nA * KK;
            #pragma unroll
            for (int k = 0; k < KK; ++k) { cpA[k] = c[k]; cpB[k] = cpA[k]; }
        }
        float SA = 0.f, SB = 0.f;
        #pragma unroll
        for (int k = 0; k < KK; ++k) {
            cpA[k] = __expf(cpA[k]); SA += cpA[k];
            cpB[k] = __expf(cpB[k]); SB += cpB[k];
        }
        float iA = 1.f / SA, iB = 1.f / SB;
        #pragma unroll
        for (int k = 0; k < KK; ++k) { cpA[k] *= iA; cpB[k] *= iB; }
    }

    // ---- attention logits: cp[k] <- exp(lg)*cp[k] in place; sums ----
    float SeA = 0.f, SmA = 0.f, SeB = 0.f, SmB = 0.f;
    t_chunk<0, 2>(sw, fA, fB, cpA, cpB, qsKA, qbkA, qsKB, qbkB, SeA, SmA, SeB, SmB);
    t_chunk<8, 2>(sw, fA, fB, cpA, cpB, qsKA, qbkA, qsKB, qbkB, SeA, SmA, SeB, SmB);
    t_chunk<16, 1>(sw, fA, fB, cpA, cpB, qsKA, qbkA, qsKB, qbkB, SeA, SmA, SeB, SmB);
    // f's register live range ends here (phase B re-streams feat from L2)

    const float invA = 1.f / SeA, invB = 1.f / SeB;
    const float gA = vfA * invA, gB = vfB * invB;
    const float s2A = SmA * invA, s2B = SmB * invB;

    // ================= PHASE B: output accumulation ======================
    u64 OA[10], OB[10];
    {
        const u64* bp = reinterpret_cast<const u64*>(sw + SBOUT);
        #pragma unroll
        for (int i = 0; i < 10; ++i) { OA[i] = bp[i]; OB[i] = bp[i]; }
    }
    // rank-4 update (sflow dies)
    {
        float cAr[4] = { vfA * s2A * sA0, vfA * s2A * sA1, vfA * s2A * sA2, vfA };
        float cBr[4] = { vfB * s2B * sB0, vfB * s2B * sB1, vfB * s2B * sB2, vfB };
        #pragma unroll
        for (int j = 0; j < 4; ++j) {
            u64 aA = pack2(cAr[j], cAr[j]), aB = pack2(cBr[j], cBr[j]);
            const ulonglong2* r = reinterpret_cast<const ulonglong2*>(sw + SP + j * KP);
            #pragma unroll
            for (int i = 0; i < 5; ++i) {
                ulonglong2 ww = r[i];
                OA[2 * i]     = ffma2(ww.x, aA, OA[2 * i]);
                OA[2 * i + 1] = ffma2(ww.y, aA, OA[2 * i + 1]);
                OB[2 * i]     = ffma2(ww.x, aB, OB[2 * i]);
                OB[2 * i + 1] = ffma2(ww.y, aB, OB[2 * i + 1]);
            }
        }
    }
    // a2 @ G (cp dies progressively)
    #pragma unroll
    for (int k = 0; k < KK; ++k) {
        float avA = cpA[k] * gA, avB = cpB[k] * gB;
        u64 aA = pack2(avA, avA), aB = pack2(avB, avB);
        const ulonglong2* r = reinterpret_cast<const ulonglong2*>(sw + SG + k * KP);
        #pragma unroll
        for (int i = 0; i < 5; ++i) {
            ulonglong2 ww = r[i];
            OA[2 * i]     = ffma2(ww.x, aA, OA[2 * i]);
            OA[2 * i + 1] = ffma2(ww.y, aA, OA[2 * i + 1]);
            OB[2 * i]     = ffma2(ww.x, aB, OB[2 * i]);
            OB[2 * i + 1] = ffma2(ww.y, aB, OB[2 * i + 1]);
        }
    }
    // f @ WT1, re-streaming feat from global (L2-hot)
    {
        const float4* fpA = reinterpret_cast<const float4*>(feat + (size_t)nA * 32);
        const float4* fpB = reinterpret_cast<const float4*>(feat + (size_t)nB * 32);
        #pragma unroll
        for (int i = 0; i < 8; ++i) {
            float4 vA = fpA[i];
            float4 vB = fpB[i];
            float xa[4] = { vA.x, vA.y, vA.z, vA.w };
            float xb[4] = { vB.x, vB.y, vB.z, vB.w };
            #pragma unroll
            for (int j = 0; j < 4; ++j) {
                const int d = 4 * i + j;
                u64 fa = pack2(xa[j], xa[j]);
                u64 fb = pack2(xb[j], xb[j]);
                const ulonglong2* r = reinterpret_cast<const ulonglong2*>(sw + SFB + d * 44 + 24);
                #pragma unroll
                for (int q = 0; q < 5; ++q) {
                    ulonglong2 ww = r[q];
                    OA[2 * q]     = ffma2(ww.x, fa, OA[2 * q]);
                    OA[2 * q + 1] = ffma2(ww.y, fa, OA[2 * q + 1]);
                    OB[2 * q]     = ffma2(ww.x, fb, OB[2 * q]);
                    OB[2 * q + 1] = ffma2(ww.y, fb, OB[2 * q + 1]);
                }
            }
        }
    }

    // ---- store ----
    float oA[20], oB[20];
    #pragma unroll
    for (int i = 0; i < 10; ++i) {
        unpack2(OA[i], oA[2 * i], oA[2 * i + 1]);
        unpack2(OB[i], oB[2 * i], oB[2 * i + 1]);
    }
    if (pair) {
        float2* op2 = reinterpret_cast<float2*>(out + (size_t)nA * KK);
        #pragma unroll
        for (int j = 0; j < 19; ++j) {
            float2 v;
            v.x = (2 * j     < KK) ? oA[2 * j]     : oB[2 * j - KK];
            v.y = (2 * j + 1 < KK) ? oA[2 * j + 1] : oB[2 * j + 1 - KK];
            op2[j] = v;
        }
    } else {
        float* op = out + (size_t)nA * KK;
        #pragma unroll
        for (int k = 0; k < KK; ++k) op[k] = oA[k];
    }
}

// ============================================================================
extern "C" void kernel_launch(void* const* d_in, const int* in_sizes, int n_in,
                              void* d_out, int out_size)
{
    const float* feat      = (const float*)d_in[0];
    const float* sflow     = (const float*)d_in[1];
    const float* cpred     = (const float*)d_in[2];
    const float* z         = (const float*)d_in[3];
    const float* select_w1 = (const float*)d_in[4];
    const float* bn_gamma  = (const float*)d_in[5];
    const float* bn_beta   = (const float*)d_in[6];
    const float* bn_mean   = (const float*)d_in[7];
    const float* bn_var    = (const float*)d_in[8];
    const float* select_w2 = (const float*)d_in[9];
    const float* select_b2 = (const float*)d_in[10];
    const float* wq        = (const float*)d_in[11];
    const float* bq        = (const float*)d_in[12];
    const float* wk        = (const float*)d_in[13];
    const float* bk        = (const float*)d_in[14];
    const float* wv        = (const float*)d_in[15];
    const float* bv        = (const float*)d_in[16];
    const float* wo        = (const float*)d_in[17];
    const float* bo        = (const float*)d_in[18];
    const float* wt        = (const float*)d_in[19];
    const float* bt        = (const float*)d_in[20];
    const float* w_out     = (const float*)d_in[21];
    const float* b_out     = (const float*)d_in[22];
    const float* w_gen     = (const float*)d_in[23];
    const float* b_gen     = (const float*)d_in[24];
    float* out = (float*)d_out;

    const int N = in_sizes[0] / 32;

    setup_kernel<<<1, 1024>>>(z, select_w1, bn_gamma, bn_beta, bn_mean, bn_var,
                              select_w2, select_b2, wq, bq, wk, bk, wv, bv,
                              wo, bo, wt, bt, w_out, b_out, w_gen, b_gen);

    const int pairs = (N + 1) / 2;
    refine_kernel<<<(pairs + 63) / 64, 64>>>(feat, sflow, cpred, out, N);
}